// round 16
// baseline (speedup 1.0000x reference)
#include <cuda_runtime.h>
#include <math.h>
#include <float.h>

#define NN 50000
#define EE 800000
#define FF 128
#define HH 64
#define HEADS 4
#define LL 3
#define GG 64
#define NCLS 2
#define EPS 1e-5f
#define CHUNKS 256
#define CHSZ ((NN + CHUNKS - 1) / CHUNKS)

// ---------------- scratch (device globals) ----------------------------------
__device__ __align__(16) float g_h[NN * HH];
__device__ __align__(16) float g_hw[NN * HH];
__device__ __align__(16) float g_acc[NN * HH];
__device__ __align__(16) float g_hg[NN * HEADS * HH];
__device__ float g_dinv[NN];
__device__ int   g_degi[NN];
__device__ int   g_off[NN];
__device__ int   g_cur[NN];
__device__ int   g_srcs[EE];
__device__ int   g_csum[CHUNKS];
__device__ int   g_cbase[CHUNKS];
__device__ float g_as[NN * HEADS];
__device__ float g_ad[NN * HEADS];
__device__ float g_aself[NN * HEADS];
__device__ __align__(16) float g_alpha[EE * HEADS];
__device__ double g_bnsum[HH];
__device__ double g_bnsq[HH];
__device__ __align__(16) float g_bnmu[HH];
__device__ __align__(16) float g_bnrstd[HH];
__device__ unsigned g_bncnt;
__device__ float g_psum[GG * HH];
__device__ float g_pmax[GG * HH];
__device__ float g_pcnt[GG];
// transposed weights: WT[m][k] so k is contiguous for LDS.128 staging
__device__ __align__(16) float g_WiT[HH * FF];            // [64][128]
__device__ __align__(16) float g_gcnWT[LL * HH * HH];     // 3 x [64][64]
__device__ __align__(16) float g_WgT[HEADS * HH * HH];    // [256][64]

// ---------------- helpers ----------------------------------------------------
__device__ __forceinline__ void atomicMaxF(float* addr, float v) {
    if (v >= 0.f) atomicMax((int*)addr, __float_as_int(v));
    else          atomicMin((unsigned int*)addr, __float_as_uint(v));
}
__device__ __forceinline__ float lrelu02(float x) { return x > 0.f ? x : 0.2f * x; }

// ---------------- weight transpose (once per launch, ~33K elems) ---------------
__global__ void transpose_weights(const float* __restrict__ Wi,
                                  const float* __restrict__ gcnW,
                                  const float* __restrict__ Wg) {
    int i = blockIdx.x * blockDim.x + threadIdx.x;
    if (i < HH * FF) {               // WiT[m][k] = Wi[k][m]
        int m = i / FF, k = i % FF;
        g_WiT[i] = Wi[k * HH + m];
    }
    if (i < LL * HH * HH) {          // gcnWT[l][m][k] = gcnW[l][k][m]
        int l = i / (HH * HH);
        int r = i - l * (HH * HH);
        int m = r / HH, k = r % HH;
        g_gcnWT[i] = gcnW[l * HH * HH + k * HH + m];
    }
    if (i < HEADS * HH * HH) {       // WgT[m][k] = Wg[k][m]
        int m = i / HH, k = i % HH;
        g_WgT[i] = Wg[k * (HEADS * HH) + m];
    }
}

// ---------------- tiled GEMM, dual LDS.128 inner loop, MT output tiles ---------
// INMODE: 0 = param X, 1 = g_h, 2 = fused BN: X := relu((g_acc-mu)*rstd+beta)+g_h
// HOUT (INMODE==2): 0 -> h_new to g_h, 1 -> h_new to g_hw  (x-blocks own disjoint rows)
// OUT: 0 -> g_h, 1 -> g_hw, 2 -> g_hg
// WSEL: 0 -> g_WiT, 1 -> g_gcnWT + layer*HH*HH, 2 -> g_WgT   (WT is [M][K])
// MT: number of 64-wide M tiles processed per block (MT>1 requires K==64, gridDim.y==1)
template <int K, int M, int INMODE, int HOUT, int OUT, int WSEL, int MT,
          bool BIAS_RELU, bool DOTS, bool SCALE_DINV>
__global__ void gemm64(const float* __restrict__ Xp, int layer,
                       const float* __restrict__ bias, const float* __restrict__ beta,
                       const float* __restrict__ att_s, const float* __restrict__ att_d) {
    const float* __restrict__ WT =
        (WSEL == 0) ? g_WiT : (WSEL == 1) ? (g_gcnWT + layer * HH * HH) : g_WgT;
    float* __restrict__ Y = (OUT == 0) ? g_h : (OUT == 1) ? g_hw : g_hg;
    __shared__ float xs[64][68];    // [node][k], k contiguous
    __shared__ float wsT[64][68];   // [m][k],    k contiguous
    const int tid = threadIdx.x;
    const int tx = tid & 15, ty = tid >> 4;
    const int nb = blockIdx.x * 64;

    // ---- stage X (once; for MT>1 K==64 so a single kc chunk) ----
    for (int kc = 0; kc < K; kc += 64) {
#pragma unroll
        for (int u = 0; u < 4; ++u) {
            int i = tid + u * 256;
            int node = i >> 4, k4 = i & 15;
            int gn = nb + node;
            float4 r = make_float4(0.f, 0.f, 0.f, 0.f);
            if (gn < NN) {
                if (INMODE == 2) {
                    float4 a = ((const float4*)g_acc)[gn * 16 + k4];
                    float4 h = ((const float4*)g_h)[gn * 16 + k4];
                    float4 mu = ((const float4*)g_bnmu)[k4];
                    float4 rs = ((const float4*)g_bnrstd)[k4];
                    float4 be = ((const float4*)beta)[k4];
                    r.x = fmaxf((a.x - mu.x) * rs.x + be.x, 0.f) + h.x;
                    r.y = fmaxf((a.y - mu.y) * rs.y + be.y, 0.f) + h.y;
                    r.z = fmaxf((a.z - mu.z) * rs.z + be.z, 0.f) + h.z;
                    r.w = fmaxf((a.w - mu.w) * rs.w + be.w, 0.f) + h.w;
                    if (MT > 1 || blockIdx.y == 0) {
                        float4* Hdst = (HOUT == 0) ? (float4*)g_h : (float4*)g_hw;
                        Hdst[gn * 16 + k4] = r;
                    }
                } else {
                    const float4* X4 = (INMODE == 0) ? (const float4*)Xp : (const float4*)g_h;
                    r = X4[gn * (K / 4) + (kc >> 2) + k4];
                }
            }
            *(float4*)&xs[node][k4 * 4] = r;
        }
        if (MT == 1) {
            // classic path: stage W chunk and accumulate (supports K>64)
            const int mb = blockIdx.y * 64;
            __shared__ float accdummy;  // (no-op; keeps structure simple)
            (void)accdummy;
#pragma unroll
            for (int u = 0; u < 4; ++u) {
                int i = tid + u * 256;
                int m = i >> 4, k4 = i & 15;
                float4 w = *(const float4*)&WT[(mb + m) * K + kc + k4 * 4];
                *(float4*)&wsT[m][k4 * 4] = w;
            }
        }
        __syncthreads();
        if (MT == 1) {
            // accumulate into persistent acc (declared below via static storage trick)
        }
        if (MT == 1 && kc + 64 < K) {
            // handled in the unified loop below
        }
        break;  // staging loop handled manually below for K>64
    }

    if (MT == 1) {
        const int mb = blockIdx.y * 64;
        float acc[4][4];
#pragma unroll
        for (int i = 0; i < 4; ++i)
#pragma unroll
            for (int j = 0; j < 4; ++j) acc[i][j] = 0.f;
        for (int kc = 0; kc < K; kc += 64) {
            if (kc > 0) {
                __syncthreads();
                // restage xs + ws for this chunk (INMODE 0/1 only reach here; K=128 input gemm)
#pragma unroll
                for (int u = 0; u < 4; ++u) {
                    int i = tid + u * 256;
                    int node = i >> 4, k4 = i & 15;
                    int gn = nb + node;
                    float4 r = make_float4(0.f, 0.f, 0.f, 0.f);
                    if (gn < NN) {
                        const float4* X4 = (INMODE == 0) ? (const float4*)Xp : (const float4*)g_h;
                        r = X4[gn * (K / 4) + (kc >> 2) + k4];
                    }
                    *(float4*)&xs[node][k4 * 4] = r;
                }
#pragma unroll
                for (int u = 0; u < 4; ++u) {
                    int i = tid + u * 256;
                    int m = i >> 4, k4 = i & 15;
                    float4 w = *(const float4*)&WT[(mb + m) * K + kc + k4 * 4];
                    *(float4*)&wsT[m][k4 * 4] = w;
                }
                __syncthreads();
            }
#pragma unroll
            for (int k = 0; k < 64; k += 4) {
                float4 xv[4], wv[4];
#pragma unroll
                for (int i = 0; i < 4; ++i) xv[i] = *(const float4*)&xs[ty + 16 * i][k];
#pragma unroll
                for (int j = 0; j < 4; ++j) wv[j] = *(const float4*)&wsT[tx + 16 * j][k];
#pragma unroll
                for (int i = 0; i < 4; ++i)
#pragma unroll
                    for (int j = 0; j < 4; ++j) {
                        acc[i][j] += xv[i].x * wv[j].x;
                        acc[i][j] += xv[i].y * wv[j].y;
                        acc[i][j] += xv[i].z * wv[j].z;
                        acc[i][j] += xv[i].w * wv[j].w;
                    }
            }
        }
#pragma unroll
        for (int i = 0; i < 4; ++i) {
            int gn = nb + ty + 16 * i;
            if (gn >= NN) continue;
            float dscale = SCALE_DINV ? g_dinv[gn] : 1.f;
#pragma unroll
            for (int j = 0; j < 4; ++j) {
                int col = tx + 16 * j;
                float v = acc[i][j];
                if (BIAS_RELU) v = fmaxf(v + bias[mb + col], 0.f);
                if (SCALE_DINV) v *= dscale;
                Y[gn * M + mb + col] = v;
            }
        }
        if (DOTS) {
            const int head = blockIdx.y;
#pragma unroll
            for (int i = 0; i < 4; ++i) {
                int gn = nb + ty + 16 * i;
                float ps = 0.f, pd = 0.f;
#pragma unroll
                for (int j = 0; j < 4; ++j) {
                    int c = tx + 16 * j;
                    ps += acc[i][j] * att_s[head * HH + c];
                    pd += acc[i][j] * att_d[head * HH + c];
                }
#pragma unroll
                for (int o = 8; o; o >>= 1) {
                    ps += __shfl_down_sync(0xffffffffu, ps, o, 16);
                    pd += __shfl_down_sync(0xffffffffu, pd, o, 16);
                }
                if (tx == 0 && gn < NN) {
                    atomicAdd(&g_as[gn * HEADS + head], ps);
                    atomicAdd(&g_ad[gn * HEADS + head], pd);
                }
            }
        }
    } else {
        // MT>1 path (K==64): X staged once above; loop over M tiles
#pragma unroll
        for (int mt = 0; mt < MT; ++mt) {
            const int mb = mt * 64;
#pragma unroll
            for (int u = 0; u < 4; ++u) {
                int i = tid + u * 256;
                int m = i >> 4, k4 = i & 15;
                float4 w = *(const float4*)&WT[(mb + m) * K + k4 * 4];
                *(float4*)&wsT[m][k4 * 4] = w;
            }
            __syncthreads();
            float acc[4][4];
#pragma unroll
            for (int i = 0; i < 4; ++i)
#pragma unroll
                for (int j = 0; j < 4; ++j) acc[i][j] = 0.f;
#pragma unroll
            for (int k = 0; k < 64; k += 4) {
                float4 xv[4], wv[4];
#pragma unroll
                for (int i = 0; i < 4; ++i) xv[i] = *(const float4*)&xs[ty + 16 * i][k];
#pragma unroll
                for (int j = 0; j < 4; ++j) wv[j] = *(const float4*)&wsT[tx + 16 * j][k];
#pragma unroll
                for (int i = 0; i < 4; ++i)
#pragma unroll
                    for (int j = 0; j < 4; ++j) {
                        acc[i][j] += xv[i].x * wv[j].x;
                        acc[i][j] += xv[i].y * wv[j].y;
                        acc[i][j] += xv[i].z * wv[j].z;
                        acc[i][j] += xv[i].w * wv[j].w;
                    }
            }
#pragma unroll
            for (int i = 0; i < 4; ++i) {
                int gn = nb + ty + 16 * i;
                if (gn >= NN) continue;
                float dscale = SCALE_DINV ? g_dinv[gn] : 1.f;
#pragma unroll
                for (int j = 0; j < 4; ++j) {
                    int col = tx + 16 * j;
                    float v = acc[i][j];
                    if (BIAS_RELU) v = fmaxf(v + bias[mb + col], 0.f);
                    if (SCALE_DINV) v *= dscale;
                    Y[gn * M + mb + col] = v;
                }
            }
            if (DOTS) {
                const int head = mt;
#pragma unroll
                for (int i = 0; i < 4; ++i) {
                    int gn = nb + ty + 16 * i;
                    float ps = 0.f, pd = 0.f;
#pragma unroll
                    for (int j = 0; j < 4; ++j) {
                        int c = tx + 16 * j;
                        ps += acc[i][j] * att_s[head * HH + c];
                        pd += acc[i][j] * att_d[head * HH + c];
                    }
#pragma unroll
                    for (int o = 8; o; o >>= 1) {
                        ps += __shfl_down_sync(0xffffffffu, ps, o, 16);
                        pd += __shfl_down_sync(0xffffffffu, pd, o, 16);
                    }
                    if (tx == 0 && gn < NN) {
                        atomicAdd(&g_as[gn * HEADS + head], ps);
                        atomicAdd(&g_ad[gn * HEADS + head], pd);
                    }
                }
            }
            __syncthreads();   // protect wsT before next mt restage
        }
    }
}

// ---------------- CSR build + misc init ---------------------------------------
__global__ void init_misc() {
    int i = blockIdx.x * blockDim.x + threadIdx.x;
    if (i < NN) g_degi[i] = 0;
    if (i < NN * HEADS) { g_as[i] = 0.f; g_ad[i] = 0.f; }
    if (i < GG * HH) { g_psum[i] = 0.f; g_pmax[i] = -FLT_MAX; }
    if (i < GG) g_pcnt[i] = 0.f;
    if (i < HH) { g_bnsum[i] = 0.0; g_bnsq[i] = 0.0; }
}
__global__ void hist_dst(const int* __restrict__ ei) {
    int e = blockIdx.x * blockDim.x + threadIdx.x;
    if (e < EE) atomicAdd(&g_degi[ei[EE + e]], 1);
}
__global__ void chunk_sums() {
    int w = (blockIdx.x * blockDim.x + threadIdx.x) >> 5;
    int lane = threadIdx.x & 31;
    if (w >= CHUNKS) return;
    int i0 = w * CHSZ, i1 = min(i0 + CHSZ, NN);
    int s = 0;
    for (int i = i0 + lane; i < i1; i += 32) s += g_degi[i];
#pragma unroll
    for (int o = 16; o; o >>= 1) s += __shfl_down_sync(0xffffffffu, s, o);
    if (lane == 0) g_csum[w] = s;
}
__global__ void chunk_scan() {
    int t = threadIdx.x;
    int lane = t & 31, wid = t >> 5;
    int v = g_csum[t];
    int x = v;
#pragma unroll
    for (int o = 1; o < 32; o <<= 1) {
        int u = __shfl_up_sync(0xffffffffu, x, o);
        if (lane >= o) x += u;
    }
    __shared__ int ws[8];
    if (lane == 31) ws[wid] = x;
    __syncthreads();
    if (wid == 0 && lane < 8) {
        int w = ws[lane];
#pragma unroll
        for (int o = 1; o < 8; o <<= 1) {
            int u = __shfl_up_sync(0xffu, w, o);
            if (lane >= o) w += u;
        }
        ws[lane] = w;
    }
    __syncthreads();
    g_cbase[t] = x + (wid ? ws[wid - 1] : 0) - v;
}
__global__ void fill_offsets() {
    int w = (blockIdx.x * blockDim.x + threadIdx.x) >> 5;
    int lane = threadIdx.x & 31;
    if (w >= CHUNKS) return;
    int run = g_cbase[w];
    int i0 = w * CHSZ, i1 = min(i0 + CHSZ, NN);
    for (int base = i0; base < i1; base += 32) {
        int i = base + lane;
        int d = (i < i1) ? g_degi[i] : 0;
        int x = d;
#pragma unroll
        for (int o = 1; o < 32; o <<= 1) {
            int u = __shfl_up_sync(0xffffffffu, x, o);
            if (lane >= o) x += u;
        }
        if (i < i1) {
            int off = run + x - d;
            g_off[i] = off;
            g_cur[i] = off;
            g_dinv[i] = rsqrtf((float)d + 1.f);
        }
        run += __shfl_sync(0xffffffffu, x, 31);
    }
}
__global__ void fill_csr(const int* __restrict__ ei) {
    int e = blockIdx.x * blockDim.x + threadIdx.x;
    if (e >= EE) return;
    int src = ei[e], dst = ei[EE + e];
    int pos = atomicAdd(&g_cur[dst], 1);
    g_srcs[pos] = src;
}

// ---------------- GCN gather (R10 proven: 16 thr/node float4) ------------------
__global__ void gcn_gather() {
    int t = threadIdx.x;
    int c4 = t & 15;
    int n = blockIdx.x * 16 + (t >> 4);
    const float4* hw4 = (const float4*)g_hw;
    float dn = g_dinv[n];
    int start = g_off[n], deg = g_degi[n];
    float4 acc = hw4[n * 16 + c4];
    int k = 0;
    for (; k + 4 <= deg; k += 4) {
        int s0 = g_srcs[start + k], s1 = g_srcs[start + k + 1];
        int s2 = g_srcs[start + k + 2], s3 = g_srcs[start + k + 3];
        float4 v0 = hw4[s0 * 16 + c4], v1 = hw4[s1 * 16 + c4];
        float4 v2 = hw4[s2 * 16 + c4], v3 = hw4[s3 * 16 + c4];
        acc.x += (v0.x + v1.x) + (v2.x + v3.x);
        acc.y += (v0.y + v1.y) + (v2.y + v3.y);
        acc.z += (v0.z + v1.z) + (v2.z + v3.z);
        acc.w += (v0.w + v1.w) + (v2.w + v3.w);
    }
    for (; k < deg; ++k) {
        int s0 = g_srcs[start + k];
        float4 v0 = hw4[s0 * 16 + c4];
        acc.x += v0.x; acc.y += v0.y; acc.z += v0.z; acc.w += v0.w;
    }
    acc.x *= dn; acc.y *= dn; acc.z *= dn; acc.w *= dn;
    ((float4*)g_acc)[n * 16 + c4] = acc;
}

// ---------------- BN: fused stats + finalize (128 blocks, proven) --------------
__global__ void bn_stats_fin(const float* __restrict__ gamma) {
    __shared__ double ss[8][HH];
    __shared__ double sq[8][HH];
    __shared__ bool is_last;
    int c = threadIdx.x, ty = threadIdx.y;
    double s = 0.0, q = 0.0;
    for (int r = blockIdx.x * 8 + ty; r < NN; r += gridDim.x * 8) {
        double v = (double)g_acc[r * HH + c];
        s += v; q += v * v;
    }
    ss[ty][c] = s; sq[ty][c] = q;
    __syncthreads();
    if (ty == 0) {
#pragma unroll
        for (int t = 1; t < 8; ++t) { s += ss[t][c]; q += sq[t][c]; }
        atomicAdd(&g_bnsum[c], s);
        atomicAdd(&g_bnsq[c], q);
    }
    __threadfence();
    __syncthreads();
    if (c == 0 && ty == 0) {
        unsigned old = atomicInc(&g_bncnt, gridDim.x - 1);
        is_last = (old == gridDim.x - 1);
    }
    __syncthreads();
    if (is_last && ty == 0) {
        __threadfence();
        double mu = g_bnsum[c] / (double)NN;
        double var = g_bnsq[c] / (double)NN - mu * mu;
        g_bnmu[c] = (float)mu;
        g_bnrstd[c] = rsqrtf((float)var + EPS) * gamma[c];
        g_bnsum[c] = 0.0;
        g_bnsq[c] = 0.0;
    }
}

// ---------------- GAT (R10 proven) ---------------------------------------------
__global__ void gat_msalpha() {
    int warp = (blockIdx.x * blockDim.x + threadIdx.x) >> 5;
    int lane = threadIdx.x & 31;
    if (warp >= NN) return;
    int n = warp;
    int hd = lane & 3, k0 = lane >> 2;
    float adv = g_ad[n * HEADS + hd];
    float asv = g_as[n * HEADS + hd];
    float lg_self = lrelu02(asv + adv);
    float m = -FLT_MAX, s = 0.f;
    if (k0 == 0) { m = lg_self; s = 1.f; }
    int start = g_off[n], deg = g_degi[n];
    for (int k = k0; k < deg; k += 8) {
        int sr = g_srcs[start + k];
        float lg = lrelu02(g_as[sr * HEADS + hd] + adv);
        if (lg > m) { s = s * expf(m - lg) + 1.f; m = lg; }
        else        { s += expf(lg - m); }
    }
#pragma unroll
    for (int o = 4; o < 32; o <<= 1) {
        float mo = __shfl_xor_sync(0xffffffffu, m, o);
        float so = __shfl_xor_sync(0xffffffffu, s, o);
        float M = fmaxf(m, mo);
        s = s * expf(m - M) + so * expf(mo - M);
        m = M;
    }
    float inv = 1.f / (s + 1e-16f);
    if (lane < 4) g_aself[n * HEADS + lane] = expf(lg_self - m) * inv;
    for (int k = k0; k < deg; k += 8) {
        int sr = g_srcs[start + k];
        float lg = lrelu02(g_as[sr * HEADS + hd] + adv);
        g_alpha[(start + k) * 4 + hd] = expf(lg - m) * inv;
    }
}
__global__ void gat_gather() {
    int t = threadIdx.x;
    int c4 = t & 15;
    int n = blockIdx.x * 16 + (t >> 4);
    const float4* hg4 = (const float4*)g_hg;
    int base = n * 64;
    float a0 = g_aself[n * 4 + 0], a1 = g_aself[n * 4 + 1];
    float a2 = g_aself[n * 4 + 2], a3 = g_aself[n * 4 + 3];
    float4 v0 = hg4[base + c4], v1 = hg4[base + 16 + c4];
    float4 v2 = hg4[base + 32 + c4], v3 = hg4[base + 48 + c4];
    float4 acc;
    acc.x = a0 * v0.x + a1 * v1.x + a2 * v2.x + a3 * v3.x;
    acc.y = a0 * v0.y + a1 * v1.y + a2 * v2.y + a3 * v3.y;
    acc.z = a0 * v0.z + a1 * v1.z + a2 * v2.z + a3 * v3.z;
    acc.w = a0 * v0.w + a1 * v1.w + a2 * v2.w + a3 * v3.w;
    int start = g_off[n], deg = g_degi[n];
    for (int k = 0; k < deg; ++k) {
        int pos = start + k;
        float4 al = ((const float4*)g_alpha)[pos];
        int sr = g_srcs[pos];
        int b = sr * 64;
        float4 u0 = hg4[b + c4], u1 = hg4[b + 16 + c4];
        float4 u2 = hg4[b + 32 + c4], u3 = hg4[b + 48 + c4];
        acc.x += al.x * u0.x + al.y * u1.x + al.z * u2.x + al.w * u3.x;
        acc.y += al.x * u0.y + al.y * u1.y + al.z * u2.y + al.w * u3.y;
        acc.z += al.x * u0.z + al.y * u1.z + al.z * u2.z + al.w * u3.z;
        acc.w += al.x * u0.w + al.y * u1.w + al.z * u2.w + al.w * u3.w;
    }
    acc.x *= 0.25f; acc.y *= 0.25f; acc.z *= 0.25f; acc.w *= 0.25f;
    ((float4*)g_acc)[n * 16 + c4] = acc;
}

// ---------------- pooling (fused GAT BN+ELU+residual from g_hw) + MLP ------------
__global__ void pool_fused(const int* __restrict__ batch, const float* __restrict__ beta) {
    int c = threadIdx.x;
    int n0 = blockIdx.x * 128;
    int n1 = min(n0 + 128, NN);
    if (n0 >= NN) return;
    float mu = g_bnmu[c], rs = g_bnrstd[c], be = beta[c];
    int cur = batch[n0];
    float sum = 0.f, mx = -FLT_MAX;
    int cnt = 0;
    for (int n = n0; n < n1; ++n) {
        int b = batch[n];
        if (b != cur) {
            atomicAdd(&g_psum[cur * HH + c], sum);
            atomicMaxF(&g_pmax[cur * HH + c], mx);
            if (c == 0) atomicAdd(&g_pcnt[cur], (float)cnt);
            sum = 0.f; mx = -FLT_MAX; cnt = 0; cur = b;
        }
        float a = g_acc[n * HH + c];
        float v = (a - mu) * rs + be;
        v = (v > 0.f ? v : expf(v) - 1.f) + g_hw[n * HH + c];
        sum += v;
        mx = fmaxf(mx, v);
        cnt++;
    }
    atomicAdd(&g_psum[cur * HH + c], sum);
    atomicMaxF(&g_pmax[cur * HH + c], mx);
    if (c == 0) atomicAdd(&g_pcnt[cur], (float)cnt);
}
__global__ void mlp_kernel(const float* __restrict__ c1W, const float* __restrict__ c1b,
                           const float* __restrict__ c2W, const float* __restrict__ c2b,
                           const float* __restrict__ c3W, const float* __restrict__ c3b,
                           float* __restrict__ out) {
    __shared__ float z[2 * HH];
    __shared__ float z1[HH];
    __shared__ float z2[HH / 2];
    int g = blockIdx.x, t = threadIdx.x;
    if (t < HH) {
        float cnt = g_pcnt[g];
        float mean = g_psum[g * HH + t] / fmaxf(cnt, 1.f);
        float mx = g_pmax[g * HH + t];
        if (cnt < 0.5f) mx = 0.f;
        z[t] = mean;
        z[HH + t] = mx;
    }
    __syncthreads();
    if (t < HH) {
        float a = c1b[t];
#pragma unroll 4
        for (int k = 0; k < 2 * HH; ++k) a += z[k] * c1W[k * HH + t];
        z1[t] = fmaxf(a, 0.f);
    }
    __syncthreads();
    if (t < HH / 2) {
        float a = c2b[t];
#pragma unroll 4
        for (int k = 0; k < HH; ++k) a += z1[k] * c2W[k * (HH / 2) + t];
        z2[t] = fmaxf(a, 0.f);
    }
    __syncthreads();
    if (t < NCLS) {
        float a = c3b[t];
#pragma unroll
        for (int k = 0; k < HH / 2; ++k) a += z2[k] * c3W[k * NCLS + t];
        out[g * NCLS + t] = a;
    }
}

// ---------------- launch ----------------------------------------------------
extern "C" void kernel_launch(void* const* d_in, const int* in_sizes, int n_in,
                              void* d_out, int out_size) {
    const float* x       = (const float*)d_in[0];
    const int*   ei      = (const int*)d_in[1];
    const int*   batch   = (const int*)d_in[2];
    const float* Wi      = (const float*)d_in[3];
    const float* bi      = (const float*)d_in[4];
    const float* gcn_W   = (const float*)d_in[5];
    // d_in[6] gcn_b cancels under training-mode BN
    const float* gcn_gamma = (const float*)d_in[7];
    const float* gcn_beta  = (const float*)d_in[8];
    const float* Wg      = (const float*)d_in[9];
    // d_in[10] bg cancels under BN
    const float* att_src = (const float*)d_in[11];
    const float* att_dst = (const float*)d_in[12];
    const float* gat_gamma = (const float*)d_in[13];
    const float* gat_beta  = (const float*)d_in[14];
    const float* c1_W = (const float*)d_in[15];
    const float* c1_b = (const float*)d_in[16];
    const float* c2_W = (const float*)d_in[17];
    const float* c2_b = (const float*)d_in[18];
    const float* c3_W = (const float*)d_in[19];
    const float* c3_b = (const float*)d_in[20];
    float* out = (float*)d_out;

    const int node_blocks = (NN + 63) / 64;
    const int g16_blocks = NN / 16;
    const int warp_blocks = (NN * 32 + 255) / 256;

    transpose_weights<<<(HEADS * HH * HH + 255) / 256, 256>>>(Wi, gcn_W, Wg);  // 1
    init_misc<<<(NN * HEADS + 255) / 256, 256>>>();                            // 2
    hist_dst<<<(EE + 255) / 256, 256>>>(ei);                                   // 3
    gemm64<FF, HH, 0, 0, 0, 0, 1, true, false, false><<<dim3(node_blocks, 1), 256>>>(
        x, 0, bi, nullptr, nullptr, nullptr);                                  // 4 <- profiled
    chunk_sums<<<32, 256>>>();
    chunk_scan<<<1, 256>>>();
    fill_offsets<<<32, 256>>>();
    fill_csr<<<(EE + 255) / 256, 256>>>(ei);

    // GCN layer 0
    gemm64<HH, HH, 1, 0, 1, 1, 1, false, false, true><<<dim3(node_blocks, 1), 256>>>(
        nullptr, 0, nullptr, nullptr, nullptr, nullptr);
    gcn_gather<<<g16_blocks, 256>>>();
    bn_stats_fin<<<128, dim3(HH, 8)>>>(gcn_gamma);
    // GCN layers 1,2: fused BN(prev)+ReLU+residual in staging
    for (int l = 1; l < LL; ++l) {
        gemm64<HH, HH, 2, 0, 1, 1, 1, false, false, true><<<dim3(node_blocks, 1), 256>>>(
            nullptr, l, nullptr, gcn_beta + (l - 1) * HH, nullptr, nullptr);
        gcn_gather<<<g16_blocks, 256>>>();
        bn_stats_fin<<<128, dim3(HH, 8)>>>(gcn_gamma + l * HH);
    }

    // GAT: single-y grid, MT=4 internal M tiles — X (BN staging) done ONCE
    gemm64<HH, HEADS * HH, 2, 1, 2, 2, 4, false, true, false><<<dim3(node_blocks, 1), 256>>>(
        nullptr, 0, nullptr, gcn_beta + 2 * HH, att_src, att_dst);
    gat_msalpha<<<warp_blocks, 256>>>();
    gat_gather<<<g16_blocks, 256>>>();
    bn_stats_fin<<<128, dim3(HH, 8)>>>(gat_gamma);

    // pooling (fused GAT BN+ELU+residual) + MLP
    pool_fused<<<(NN + 127) / 128, HH>>>(batch, gat_beta);
    mlp_kernel<<<GG, 128>>>(c1_W, c1_b, c2_W, c2_b, c3_W, c3_b, out);
}

// round 17
// speedup vs baseline: 1.0211x; 1.0211x over previous
#include <cuda_runtime.h>
#include <math.h>
#include <float.h>

#define NN 50000
#define EE 800000
#define FF 128
#define HH 64
#define HEADS 4
#define LL 3
#define GG 64
#define NCLS 2
#define EPS 1e-5f
#define CHUNKS 256
#define CHSZ ((NN + CHUNKS - 1) / CHUNKS)

// ---------------- scratch (device globals) ----------------------------------
__device__ __align__(16) float g_h[NN * HH];
__device__ __align__(16) float g_hw[NN * HH];
__device__ __align__(16) float g_acc[NN * HH];
__device__ __align__(16) float g_hg[NN * HEADS * HH];
__device__ float g_dinv[NN];
__device__ int   g_degi[NN];
__device__ int   g_off[NN];
__device__ int   g_cur[NN];
__device__ int   g_srcs[EE];
__device__ int   g_csum[CHUNKS];
__device__ int   g_cbase[CHUNKS];
__device__ unsigned g_scancnt;
__device__ int   g_scandone;
__device__ float g_as[NN * HEADS];
__device__ float g_ad[NN * HEADS];
__device__ float g_aself[NN * HEADS];
__device__ __align__(16) float g_alpha[EE * HEADS];
__device__ double g_bnsum[HH];
__device__ double g_bnsq[HH];
__device__ __align__(16) float g_bnmu[HH];
__device__ __align__(16) float g_bnrstd[HH];
__device__ unsigned g_bncnt;
__device__ float g_psum[GG * HH];
__device__ float g_pmax[GG * HH];
__device__ float g_pcnt[GG];
// transposed weights: WT[m][k] so k is contiguous for LDS.128 staging
__device__ __align__(16) float g_WiT[HH * FF];
__device__ __align__(16) float g_gcnWT[LL * HH * HH];
__device__ __align__(16) float g_WgT[HEADS * HH * HH];

// ---------------- helpers ----------------------------------------------------
__device__ __forceinline__ void atomicMaxF(float* addr, float v) {
    if (v >= 0.f) atomicMax((int*)addr, __float_as_int(v));
    else          atomicMin((unsigned int*)addr, __float_as_uint(v));
}
__device__ __forceinline__ float lrelu02(float x) { return x > 0.f ? x : 0.2f * x; }

// ---------------- init + weight transpose (merged) -----------------------------
__global__ void init_misc(const float* __restrict__ Wi,
                          const float* __restrict__ gcnW,
                          const float* __restrict__ Wg) {
    int i = blockIdx.x * blockDim.x + threadIdx.x;
    if (i < NN) g_degi[i] = 0;
    if (i < NN * HEADS) { g_as[i] = 0.f; g_ad[i] = 0.f; }
    if (i < GG * HH) { g_psum[i] = 0.f; g_pmax[i] = -FLT_MAX; }
    if (i < GG) g_pcnt[i] = 0.f;
    if (i < HH) { g_bnsum[i] = 0.0; g_bnsq[i] = 0.0; }
    if (i == 0) { g_scandone = 0; g_scancnt = 0u; }
    if (i < HH * FF) {               // WiT[m][k] = Wi[k][m]
        int m = i / FF, k = i % FF;
        g_WiT[i] = Wi[k * HH + m];
    }
    if (i < LL * HH * HH) {          // gcnWT[l][m][k] = gcnW[l][k][m]
        int l = i / (HH * HH);
        int r = i - l * (HH * HH);
        int m = r / HH, k = r % HH;
        g_gcnWT[i] = gcnW[l * HH * HH + k * HH + m];
    }
    if (i < HEADS * HH * HH) {       // WgT[m][k] = Wg[k][m]
        int m = i / HH, k = i % HH;
        g_WgT[i] = Wg[k * (HEADS * HH) + m];
    }
}

// ---------------- tiled GEMM, dual LDS.128 inner loop (R15 proven) -------------
// INMODE: 0 = param X, 1 = g_h, 2 = fused BN: X := relu((g_acc-mu)*rstd+beta)+g_h
// HOUT (INMODE==2): 0 -> h_new to g_h (gridDim.y==1 only), 1 -> h_new to g_hw
// OUT: 0 -> g_h, 1 -> g_hw, 2 -> g_hg
// WSEL: 0 -> g_WiT, 1 -> g_gcnWT + layer*HH*HH, 2 -> g_WgT   (WT is [M][K])
template <int K, int M, int INMODE, int HOUT, int OUT, int WSEL,
          bool BIAS_RELU, bool DOTS, bool SCALE_DINV>
__global__ void gemm64(const float* __restrict__ Xp, int layer,
                       const float* __restrict__ bias, const float* __restrict__ beta,
                       const float* __restrict__ att_s, const float* __restrict__ att_d) {
    const float* __restrict__ WT =
        (WSEL == 0) ? g_WiT : (WSEL == 1) ? (g_gcnWT + layer * HH * HH) : g_WgT;
    float* __restrict__ Y = (OUT == 0) ? g_h : (OUT == 1) ? g_hw : g_hg;
    __shared__ float xs[64][68];
    __shared__ float wsT[64][68];
    const int tid = threadIdx.x;
    const int tx = tid & 15, ty = tid >> 4;
    const int nb = blockIdx.x * 64;
    const int mb = blockIdx.y * 64;
    float acc[4][4];
#pragma unroll
    for (int i = 0; i < 4; ++i)
#pragma unroll
        for (int j = 0; j < 4; ++j) acc[i][j] = 0.f;

    for (int kc = 0; kc < K; kc += 64) {
#pragma unroll
        for (int u = 0; u < 4; ++u) {
            int i = tid + u * 256;
            int node = i >> 4, k4 = i & 15;
            int gn = nb + node;
            float4 r = make_float4(0.f, 0.f, 0.f, 0.f);
            if (gn < NN) {
                if (INMODE == 2) {
                    float4 a = ((const float4*)g_acc)[gn * 16 + k4];
                    float4 h = ((const float4*)g_h)[gn * 16 + k4];
                    float4 mu = ((const float4*)g_bnmu)[k4];
                    float4 rs = ((const float4*)g_bnrstd)[k4];
                    float4 be = ((const float4*)beta)[k4];
                    r.x = fmaxf((a.x - mu.x) * rs.x + be.x, 0.f) + h.x;
                    r.y = fmaxf((a.y - mu.y) * rs.y + be.y, 0.f) + h.y;
                    r.z = fmaxf((a.z - mu.z) * rs.z + be.z, 0.f) + h.z;
                    r.w = fmaxf((a.w - mu.w) * rs.w + be.w, 0.f) + h.w;
                    if (blockIdx.y == 0) {
                        float4* Hdst = (HOUT == 0) ? (float4*)g_h : (float4*)g_hw;
                        Hdst[gn * 16 + k4] = r;
                    }
                } else {
                    const float4* X4 = (INMODE == 0) ? (const float4*)Xp : (const float4*)g_h;
                    r = X4[gn * (K / 4) + (kc >> 2) + k4];
                }
            }
            *(float4*)&xs[node][k4 * 4] = r;
        }
#pragma unroll
        for (int u = 0; u < 4; ++u) {
            int i = tid + u * 256;
            int m = i >> 4, k4 = i & 15;
            float4 w = *(const float4*)&WT[(mb + m) * K + kc + k4 * 4];
            *(float4*)&wsT[m][k4 * 4] = w;
        }
        __syncthreads();
#pragma unroll
        for (int k = 0; k < 64; k += 4) {
            float4 xv[4], wv[4];
#pragma unroll
            for (int i = 0; i < 4; ++i) xv[i] = *(const float4*)&xs[ty + 16 * i][k];
#pragma unroll
            for (int j = 0; j < 4; ++j) wv[j] = *(const float4*)&wsT[tx + 16 * j][k];
#pragma unroll
            for (int i = 0; i < 4; ++i)
#pragma unroll
                for (int j = 0; j < 4; ++j) {
                    acc[i][j] += xv[i].x * wv[j].x;
                    acc[i][j] += xv[i].y * wv[j].y;
                    acc[i][j] += xv[i].z * wv[j].z;
                    acc[i][j] += xv[i].w * wv[j].w;
                }
        }
        __syncthreads();
    }
#pragma unroll
    for (int i = 0; i < 4; ++i) {
        int gn = nb + ty + 16 * i;
        if (gn >= NN) continue;
        float dscale = SCALE_DINV ? g_dinv[gn] : 1.f;
#pragma unroll
        for (int j = 0; j < 4; ++j) {
            int col = tx + 16 * j;
            float v = acc[i][j];
            if (BIAS_RELU) v = fmaxf(v + bias[mb + col], 0.f);
            if (SCALE_DINV) v *= dscale;
            Y[gn * M + mb + col] = v;
        }
    }
    if (DOTS) {
        const int head = blockIdx.y;
#pragma unroll
        for (int i = 0; i < 4; ++i) {
            int gn = nb + ty + 16 * i;
            float ps = 0.f, pd = 0.f;
#pragma unroll
            for (int j = 0; j < 4; ++j) {
                int c = tx + 16 * j;
                ps += acc[i][j] * att_s[head * HH + c];
                pd += acc[i][j] * att_d[head * HH + c];
            }
#pragma unroll
            for (int o = 8; o; o >>= 1) {
                ps += __shfl_down_sync(0xffffffffu, ps, o, 16);
                pd += __shfl_down_sync(0xffffffffu, pd, o, 16);
            }
            if (tx == 0 && gn < NN) {
                atomicAdd(&g_as[gn * HEADS + head], ps);
                atomicAdd(&g_ad[gn * HEADS + head], pd);
            }
        }
    }
}

// ---------------- CSR build ----------------------------------------------------
__global__ void hist_dst(const int* __restrict__ ei) {
    int e = blockIdx.x * blockDim.x + threadIdx.x;
    if (e < EE) atomicAdd(&g_degi[ei[EE + e]], 1);
}
// Fused chunk_sums + chunk_scan + fill_offsets: 32 blocks x 256 threads, all
// co-resident (32 << 148 SMs) so the counter-based grid sync cannot deadlock.
// g_scancnt wraps via atomicInc; g_scandone reset by init_misc each replay.
__global__ void csr_scan_fused() {
    __shared__ bool is_last;
    int gw = blockIdx.x * 8 + (threadIdx.x >> 5);   // global warp = chunk id (0..255)
    int lane = threadIdx.x & 31;
    int t = threadIdx.x;
    // phase 1: per-chunk sums
    int i0 = gw * CHSZ, i1 = min(i0 + CHSZ, NN);
    int s = 0;
    for (int i = i0 + lane; i < i1; i += 32) s += g_degi[i];
#pragma unroll
    for (int o = 16; o; o >>= 1) s += __shfl_down_sync(0xffffffffu, s, o);
    if (lane == 0) g_csum[gw] = s;
    __threadfence();
    __syncthreads();
    if (t == 0) {
        unsigned old = atomicInc(&g_scancnt, 31u);
        is_last = (old == 31u);
    }
    __syncthreads();
    // phase 2: last block scans the 256 chunk sums
    if (is_last) {
        __threadfence();
        int v = g_csum[t];
        int x = v;
        int ln = t & 31, wd = t >> 5;
#pragma unroll
        for (int o = 1; o < 32; o <<= 1) {
            int u = __shfl_up_sync(0xffffffffu, x, o);
            if (ln >= o) x += u;
        }
        __shared__ int wsum[8];
        if (ln == 31) wsum[wd] = x;
        __syncthreads();
        if (wd == 0 && ln < 8) {
            int w = wsum[ln];
#pragma unroll
            for (int o = 1; o < 8; o <<= 1) {
                int u = __shfl_up_sync(0xffu, w, o);
                if (ln >= o) w += u;
            }
            wsum[ln] = w;
        }
        __syncthreads();
        g_cbase[t] = x + (wd ? wsum[wd - 1] : 0) - v;
        __threadfence();
        __syncthreads();
        if (t == 0) atomicExch(&g_scandone, 1);
    } else {
        if (t == 0) {
            while (atomicAdd(&g_scandone, 0) == 0) { }
        }
        __syncthreads();
        __threadfence();
    }
    // phase 3: per-chunk offset fill
    int run = g_cbase[gw];
    for (int base = i0; base < i1; base += 32) {
        int i = base + lane;
        int d = (i < i1) ? g_degi[i] : 0;
        int x = d;
#pragma unroll
        for (int o = 1; o < 32; o <<= 1) {
            int u = __shfl_up_sync(0xffffffffu, x, o);
            if (lane >= o) x += u;
        }
        if (i < i1) {
            int off = run + x - d;
            g_off[i] = off;
            g_cur[i] = off;
            g_dinv[i] = rsqrtf((float)d + 1.f);
        }
        run += __shfl_sync(0xffffffffu, x, 31);
    }
}
__global__ void fill_csr(const int* __restrict__ ei) {
    int e = blockIdx.x * blockDim.x + threadIdx.x;
    if (e >= EE) return;
    int src = ei[e], dst = ei[EE + e];
    int pos = atomicAdd(&g_cur[dst], 1);
    g_srcs[pos] = src;
}

// ---------------- GCN gather (R10 proven: 16 thr/node float4) ------------------
__global__ void gcn_gather() {
    int t = threadIdx.x;
    int c4 = t & 15;
    int n = blockIdx.x * 16 + (t >> 4);
    const float4* hw4 = (const float4*)g_hw;
    float dn = g_dinv[n];
    int start = g_off[n], deg = g_degi[n];
    float4 acc = hw4[n * 16 + c4];
    int k = 0;
    for (; k + 4 <= deg; k += 4) {
        int s0 = g_srcs[start + k], s1 = g_srcs[start + k + 1];
        int s2 = g_srcs[start + k + 2], s3 = g_srcs[start + k + 3];
        float4 v0 = hw4[s0 * 16 + c4], v1 = hw4[s1 * 16 + c4];
        float4 v2 = hw4[s2 * 16 + c4], v3 = hw4[s3 * 16 + c4];
        acc.x += (v0.x + v1.x) + (v2.x + v3.x);
        acc.y += (v0.y + v1.y) + (v2.y + v3.y);
        acc.z += (v0.z + v1.z) + (v2.z + v3.z);
        acc.w += (v0.w + v1.w) + (v2.w + v3.w);
    }
    for (; k < deg; ++k) {
        int s0 = g_srcs[start + k];
        float4 v0 = hw4[s0 * 16 + c4];
        acc.x += v0.x; acc.y += v0.y; acc.z += v0.z; acc.w += v0.w;
    }
    acc.x *= dn; acc.y *= dn; acc.z *= dn; acc.w *= dn;
    ((float4*)g_acc)[n * 16 + c4] = acc;
}

// ---------------- BN: fused stats + finalize (128 blocks, proven) --------------
__global__ void bn_stats_fin(const float* __restrict__ gamma) {
    __shared__ double ss[8][HH];
    __shared__ double sq[8][HH];
    __shared__ bool is_last;
    int c = threadIdx.x, ty = threadIdx.y;
    double s = 0.0, q = 0.0;
    for (int r = blockIdx.x * 8 + ty; r < NN; r += gridDim.x * 8) {
        double v = (double)g_acc[r * HH + c];
        s += v; q += v * v;
    }
    ss[ty][c] = s; sq[ty][c] = q;
    __syncthreads();
    if (ty == 0) {
#pragma unroll
        for (int t = 1; t < 8; ++t) { s += ss[t][c]; q += sq[t][c]; }
        atomicAdd(&g_bnsum[c], s);
        atomicAdd(&g_bnsq[c], q);
    }
    __threadfence();
    __syncthreads();
    if (c == 0 && ty == 0) {
        unsigned old = atomicInc(&g_bncnt, gridDim.x - 1);
        is_last = (old == gridDim.x - 1);
    }
    __syncthreads();
    if (is_last && ty == 0) {
        __threadfence();
        double mu = g_bnsum[c] / (double)NN;
        double var = g_bnsq[c] / (double)NN - mu * mu;
        g_bnmu[c] = (float)mu;
        g_bnrstd[c] = rsqrtf((float)var + EPS) * gamma[c];
        g_bnsum[c] = 0.0;
        g_bnsq[c] = 0.0;
    }
}

// ---------------- GAT (R10 proven) ---------------------------------------------
__global__ void gat_msalpha() {
    int warp = (blockIdx.x * blockDim.x + threadIdx.x) >> 5;
    int lane = threadIdx.x & 31;
    if (warp >= NN) return;
    int n = warp;
    int hd = lane & 3, k0 = lane >> 2;
    float adv = g_ad[n * HEADS + hd];
    float asv = g_as[n * HEADS + hd];
    float lg_self = lrelu02(asv + adv);
    float m = -FLT_MAX, s = 0.f;
    if (k0 == 0) { m = lg_self; s = 1.f; }
    int start = g_off[n], deg = g_degi[n];
    for (int k = k0; k < deg; k += 8) {
        int sr = g_srcs[start + k];
        float lg = lrelu02(g_as[sr * HEADS + hd] + adv);
        if (lg > m) { s = s * expf(m - lg) + 1.f; m = lg; }
        else        { s += expf(lg - m); }
    }
#pragma unroll
    for (int o = 4; o < 32; o <<= 1) {
        float mo = __shfl_xor_sync(0xffffffffu, m, o);
        float so = __shfl_xor_sync(0xffffffffu, s, o);
        float M = fmaxf(m, mo);
        s = s * expf(m - M) + so * expf(mo - M);
        m = M;
    }
    float inv = 1.f / (s + 1e-16f);
    if (lane < 4) g_aself[n * HEADS + lane] = expf(lg_self - m) * inv;
    for (int k = k0; k < deg; k += 8) {
        int sr = g_srcs[start + k];
        float lg = lrelu02(g_as[sr * HEADS + hd] + adv);
        g_alpha[(start + k) * 4 + hd] = expf(lg - m) * inv;
    }
}
__global__ void gat_gather() {
    int t = threadIdx.x;
    int c4 = t & 15;
    int n = blockIdx.x * 16 + (t >> 4);
    const float4* hg4 = (const float4*)g_hg;
    int base = n * 64;
    float a0 = g_aself[n * 4 + 0], a1 = g_aself[n * 4 + 1];
    float a2 = g_aself[n * 4 + 2], a3 = g_aself[n * 4 + 3];
    float4 v0 = hg4[base + c4], v1 = hg4[base + 16 + c4];
    float4 v2 = hg4[base + 32 + c4], v3 = hg4[base + 48 + c4];
    float4 acc;
    acc.x = a0 * v0.x + a1 * v1.x + a2 * v2.x + a3 * v3.x;
    acc.y = a0 * v0.y + a1 * v1.y + a2 * v2.y + a3 * v3.y;
    acc.z = a0 * v0.z + a1 * v1.z + a2 * v2.z + a3 * v3.z;
    acc.w = a0 * v0.w + a1 * v1.w + a2 * v2.w + a3 * v3.w;
    int start = g_off[n], deg = g_degi[n];
    for (int k = 0; k < deg; ++k) {
        int pos = start + k;
        float4 al = ((const float4*)g_alpha)[pos];
        int sr = g_srcs[pos];
        int b = sr * 64;
        float4 u0 = hg4[b + c4], u1 = hg4[b + 16 + c4];
        float4 u2 = hg4[b + 32 + c4], u3 = hg4[b + 48 + c4];
        acc.x += al.x * u0.x + al.y * u1.x + al.z * u2.x + al.w * u3.x;
        acc.y += al.x * u0.y + al.y * u1.y + al.z * u2.y + al.w * u3.y;
        acc.z += al.x * u0.z + al.y * u1.z + al.z * u2.z + al.w * u3.z;
        acc.w += al.x * u0.w + al.y * u1.w + al.z * u2.w + al.w * u3.w;
    }
    acc.x *= 0.25f; acc.y *= 0.25f; acc.z *= 0.25f; acc.w *= 0.25f;
    ((float4*)g_acc)[n * 16 + c4] = acc;
}

// ---------------- pooling (fused GAT BN+ELU+residual from g_hw) + MLP ------------
__global__ void pool_fused(const int* __restrict__ batch, const float* __restrict__ beta) {
    int c = threadIdx.x;
    int n0 = blockIdx.x * 128;
    int n1 = min(n0 + 128, NN);
    if (n0 >= NN) return;
    float mu = g_bnmu[c], rs = g_bnrstd[c], be = beta[c];
    int cur = batch[n0];
    float sum = 0.f, mx = -FLT_MAX;
    int cnt = 0;
    for (int n = n0; n < n1; ++n) {
        int b = batch[n];
        if (b != cur) {
            atomicAdd(&g_psum[cur * HH + c], sum);
            atomicMaxF(&g_pmax[cur * HH + c], mx);
            if (c == 0) atomicAdd(&g_pcnt[cur], (float)cnt);
            sum = 0.f; mx = -FLT_MAX; cnt = 0; cur = b;
        }
        float a = g_acc[n * HH + c];
        float v = (a - mu) * rs + be;
        v = (v > 0.f ? v : expf(v) - 1.f) + g_hw[n * HH + c];
        sum += v;
        mx = fmaxf(mx, v);
        cnt++;
    }
    atomicAdd(&g_psum[cur * HH + c], sum);
    atomicMaxF(&g_pmax[cur * HH + c], mx);
    if (c == 0) atomicAdd(&g_pcnt[cur], (float)cnt);
}
__global__ void mlp_kernel(const float* __restrict__ c1W, const float* __restrict__ c1b,
                           const float* __restrict__ c2W, const float* __restrict__ c2b,
                           const float* __restrict__ c3W, const float* __restrict__ c3b,
                           float* __restrict__ out) {
    __shared__ float z[2 * HH];
    __shared__ float z1[HH];
    __shared__ float z2[HH / 2];
    int g = blockIdx.x, t = threadIdx.x;
    if (t < HH) {
        float cnt = g_pcnt[g];
        float mean = g_psum[g * HH + t] / fmaxf(cnt, 1.f);
        float mx = g_pmax[g * HH + t];
        if (cnt < 0.5f) mx = 0.f;
        z[t] = mean;
        z[HH + t] = mx;
    }
    __syncthreads();
    if (t < HH) {
        float a = c1b[t];
#pragma unroll 4
        for (int k = 0; k < 2 * HH; ++k) a += z[k] * c1W[k * HH + t];
        z1[t] = fmaxf(a, 0.f);
    }
    __syncthreads();
    if (t < HH / 2) {
        float a = c2b[t];
#pragma unroll 4
        for (int k = 0; k < HH; ++k) a += z1[k] * c2W[k * (HH / 2) + t];
        z2[t] = fmaxf(a, 0.f);
    }
    __syncthreads();
    if (t < NCLS) {
        float a = c3b[t];
#pragma unroll
        for (int k = 0; k < HH / 2; ++k) a += z2[k] * c3W[k * NCLS + t];
        out[g * NCLS + t] = a;
    }
}

// ---------------- launch ----------------------------------------------------
extern "C" void kernel_launch(void* const* d_in, const int* in_sizes, int n_in,
                              void* d_out, int out_size) {
    const float* x       = (const float*)d_in[0];
    const int*   ei      = (const int*)d_in[1];
    const int*   batch   = (const int*)d_in[2];
    const float* Wi      = (const float*)d_in[3];
    const float* bi      = (const float*)d_in[4];
    const float* gcn_W   = (const float*)d_in[5];
    // d_in[6] gcn_b cancels under training-mode BN
    const float* gcn_gamma = (const float*)d_in[7];
    const float* gcn_beta  = (const float*)d_in[8];
    const float* Wg      = (const float*)d_in[9];
    // d_in[10] bg cancels under BN
    const float* att_src = (const float*)d_in[11];
    const float* att_dst = (const float*)d_in[12];
    const float* gat_gamma = (const float*)d_in[13];
    const float* gat_beta  = (const float*)d_in[14];
    const float* c1_W = (const float*)d_in[15];
    const float* c1_b = (const float*)d_in[16];
    const float* c2_W = (const float*)d_in[17];
    const float* c2_b = (const float*)d_in[18];
    const float* c3_W = (const float*)d_in[19];
    const float* c3_b = (const float*)d_in[20];
    float* out = (float*)d_out;

    const int node_blocks = (NN + 63) / 64;
    const int g16_blocks = NN / 16;
    const int warp_blocks = (NN * 32 + 255) / 256;

    init_misc<<<(NN * HEADS + 255) / 256, 256>>>(Wi, gcn_W, Wg);   // 1
    hist_dst<<<(EE + 255) / 256, 256>>>(ei);                       // 2
    csr_scan_fused<<<32, 256>>>();                                 // 3
    gemm64<FF, HH, 0, 0, 0, 0, true, false, false><<<dim3(node_blocks, 1), 256>>>(
        x, 0, bi, nullptr, nullptr, nullptr);                      // 4 <- profiled
    fill_csr<<<(EE + 255) / 256, 256>>>(ei);                       // 5

    // GCN layer 0
    gemm64<HH, HH, 1, 0, 1, 1, false, false, true><<<dim3(node_blocks, 1), 256>>>(
        nullptr, 0, nullptr, nullptr, nullptr, nullptr);
    gcn_gather<<<g16_blocks, 256>>>();
    bn_stats_fin<<<128, dim3(HH, 8)>>>(gcn_gamma);
    // GCN layers 1,2: fused BN(prev)+ReLU+residual in staging
    for (int l = 1; l < LL; ++l) {
        gemm64<HH, HH, 2, 0, 1, 1, false, false, true><<<dim3(node_blocks, 1), 256>>>(
            nullptr, l, nullptr, gcn_beta + (l - 1) * HH, nullptr, nullptr);
        gcn_gather<<<g16_blocks, 256>>>();
        bn_stats_fin<<<128, dim3(HH, 8)>>>(gcn_gamma + l * HH);
    }

    // GAT: grid.y=4 (R15 proven); gemm applies layer-2 BN; h_new -> g_hw; fused dots
    gemm64<HH, HEADS * HH, 2, 1, 2, 2, false, true, false><<<dim3(node_blocks, 4), 256>>>(
        nullptr, 0, nullptr, gcn_beta + 2 * HH, att_src, att_dst);
    gat_msalpha<<<warp_blocks, 256>>>();
    gat_gather<<<g16_blocks, 256>>>();
    bn_stats_fin<<<128, dim3(HH, 8)>>>(gat_gamma);

    // pooling (fused GAT BN+ELU+residual) + MLP
    pool_fused<<<(NN + 127) / 128, HH>>>(batch, gat_beta);
    mlp_kernel<<<GG, 128>>>(c1_W, c1_b, c2_W, c2_b, c3_W, c3_b, out);
}